// round 10
// baseline (speedup 1.0000x reference)
#include <cuda_runtime.h>

#define T_STEPS 8192
#define NN      2048
#define NCTA    128
#define ROWS    16      // neurons (w rows) per CTA
#define NTHR    256     // threads per CTA (8 warps)
#define CPT     8       // columns per thread (2048 / 256)

// Parity double-buffered conductance + one monotonic arrival counter.
__device__ float g_buf[2][NN];
__device__ unsigned int bar_ctr;   // total arrivals = NCTA * (steps completed)

// Reset state so every graph replay is identical.
__global__ void lif_init_kernel(const float* __restrict__ g0) {
    int i = blockIdx.x * blockDim.x + threadIdx.x;
    if (i < NN) g_buf[0][i] = g0[i];
    if (i == 0) bar_ctr = 0;
}

__global__ void __launch_bounds__(NTHR, 1) lif_persistent_kernel(
    const float* __restrict__ x_in,    // [T, N]
    const float* __restrict__ w,       // [N, N] row-major
    const float* __restrict__ v_rest,  // [N]
    const float* __restrict__ tau_m,   // [N]
    const float* __restrict__ tau_g,   // [N]
    const float* __restrict__ pre_c_p, // [1]
    const float* __restrict__ post_c_p,// [1]
    const float* __restrict__ v0,      // [N]
    const float* __restrict__ g0,      // [N]
    float* __restrict__ out)           // [2, T, N]
{
    const int tid  = threadIdx.x;
    const int cta  = blockIdx.x;
    const int lane = tid & 31;
    const int warp = tid >> 5;
    const int row0 = cta * ROWS;
    const int col0 = tid * CPT;

    __shared__ float sh_part[2][8][ROWS];

    // ---- one-time: this CTA's 16 w rows live in REGISTERS (128 KB/SM) ----
    float wreg[ROWS][CPT];
    #pragma unroll
    for (int r = 0; r < ROWS; r++) {
        const float4* wp = reinterpret_cast<const float4*>(
            w + (size_t)(row0 + r) * NN + col0);
        float4 a = wp[0], b = wp[1];
        wreg[r][0] = a.x; wreg[r][1] = a.y; wreg[r][2] = a.z; wreg[r][3] = a.w;
        wreg[r][4] = b.x; wreg[r][5] = b.y; wreg[r][6] = b.z; wreg[r][7] = b.w;
    }

    // ---- per-neuron state; divisions hoisted out of the loop ----
    // tau_m = 4.0, tau_g = 2.0 (powers of two) -> reciprocal forms bit-exact.
    const float pre_c  = pre_c_p[0];
    const float post_c = post_c_p[0];
    float my_v = 0.f, my_g = 0.f, my_vrest = 0.f, inv_taum = 0.f, decay_g = 0.f;
    float x_next = 0.f;
    if (tid < ROWS) {
        int i = row0 + tid;
        my_v     = v0[i];
        my_g     = g0[i];
        my_vrest = v_rest[i];
        inv_taum = 1.0f / tau_m[i];
        decay_g  = 1.0f - 1.0f / tau_g[i];
        x_next   = __ldcs(&x_in[i]);   // prefetch x for t=0
    }
    __syncthreads();

    for (int t = 0; t < T_STEPS; t++) {
        const int par = t & 1;

        // ---- prefetch next step's x BEFORE the wait (hides under the spin) ----
        float x_cur = x_next;
        if (tid < ROWS && t + 1 < T_STEPS) {
            x_next = __ldcs(&x_in[(size_t)(t + 1) * NN + row0 + tid]);
        }

        // ---- wait until all CTAs finished step t-1 (counter = NCTA*t) ----
        // R5-proven: ONE poller per CTA, plain .cg spin.
        if (t > 0) {
            if (tid == 0) {
                const unsigned target = (unsigned)(NCTA * t);
                unsigned c;
                do {
                    asm volatile("ld.global.cg.u32 %0, [%1];"
                                 : "=r"(c) : "l"(&bar_ctr));
                } while (c < target);
            }
            __syncthreads();
        }

        // ---- load g for this step (L1-bypass; written by other SMs) ----
        float gv[CPT];
        {
            const float4 ga = __ldcg(reinterpret_cast<const float4*>(g_buf[par] + col0));
            const float4 gb = __ldcg(reinterpret_cast<const float4*>(g_buf[par] + col0 + 4));
            gv[0]=ga.x; gv[1]=ga.y; gv[2]=ga.z; gv[3]=ga.w;
            gv[4]=gb.x; gv[5]=gb.y; gv[6]=gb.z; gv[7]=gb.w;
        }

        // ---- matvec partials: 16 rows x 8 cols, scalar FFMA (R5-proven) ----
        float acc[ROWS];
        #pragma unroll
        for (int r = 0; r < ROWS; r++) {
            float s = 0.f;
            #pragma unroll
            for (int k = 0; k < CPT; k++) s = fmaf(wreg[r][k], gv[k], s);
            acc[r] = s;
        }

        // ---- intra-warp folding reduction: 16 rows over 32 lanes, 16 SHFLs ----
        #pragma unroll
        for (int r = 0; r < 8; r++) {
            bool hi = (lane & 16) != 0;
            float send = hi ? acc[r] : acc[r + 8];
            float keep = hi ? acc[r + 8] : acc[r];
            acc[r] = keep + __shfl_xor_sync(0xffffffffu, send, 16);
        }
        #pragma unroll
        for (int r = 0; r < 4; r++) {
            bool hi = (lane & 8) != 0;
            float send = hi ? acc[r] : acc[r + 4];
            float keep = hi ? acc[r + 4] : acc[r];
            acc[r] = keep + __shfl_xor_sync(0xffffffffu, send, 8);
        }
        #pragma unroll
        for (int r = 0; r < 2; r++) {
            bool hi = (lane & 4) != 0;
            float send = hi ? acc[r] : acc[r + 2];
            float keep = hi ? acc[r + 2] : acc[r];
            acc[r] = keep + __shfl_xor_sync(0xffffffffu, send, 4);
        }
        {
            bool hi = (lane & 2) != 0;
            float send = hi ? acc[0] : acc[1];
            float keep = hi ? acc[1] : acc[0];
            acc[0] = keep + __shfl_xor_sync(0xffffffffu, send, 2);
        }
        acc[0] += __shfl_xor_sync(0xffffffffu, acc[0], 1);

        if ((lane & 1) == 0) sh_part[par][warp][lane >> 1] = acc[0];
        __syncthreads();

        // ---- LIF update (division-free) : only what g_new needs pre-publish ----
        float v_new = 0.f, vpre = 0.f;
        if (tid < ROWS) {
            float y = 0.f;
            #pragma unroll
            for (int wq = 0; wq < 8; wq++) y += sh_part[par][wq][tid];
            y += x_cur;

            float I = post_c / (1.f + expf(-pre_c * y));
            float gd = my_g * decay_g;                       // == g - g/tau_g (exact)
            float v  = my_v + ((my_vrest - my_v) + I) * inv_taum;  // /4 == *0.25 (exact)
            bool spk = (v >= 30.f);
            vpre  = v;
            v_new = spk ? my_vrest : v;
            float g_new = spk ? 1.f : gd;
            my_v = v_new;
            my_g = g_new;

            __stcg(&g_buf[(t + 1) & 1][row0 + tid], g_new);   // publish g
        }

        // Release (R5-proven): warp 0 fence covers the 16 g stores, tid0 arrives.
        if (warp == 0) __threadfence();
        if (tid == 0) atomicAdd(&bar_ctr, 1u);

        // Off the inter-CTA critical path: soft sigmoid + DRAM trace stores.
        if (tid < ROWS) {
            float soft = 1.f / (1.f + expf(-(vpre - 30.f)));
            int i = row0 + tid;
            __stcs(&out[(size_t)t * NN + i], v_new);
            __stcs(&out[(size_t)T_STEPS * NN + (size_t)t * NN + i], soft);
        }
        // No trailing CTA barrier: next iteration's poll + __syncthreads gates
        // every warp; g and sh_part are parity double-buffered.
    }
}

extern "C" void kernel_launch(void* const* d_in, const int* in_sizes, int n_in,
                              void* d_out, int out_size) {
    (void)in_sizes; (void)n_in; (void)out_size;
    const float* x_in   = (const float*)d_in[0];
    const float* w      = (const float*)d_in[1];
    const float* v_rest = (const float*)d_in[2];
    const float* tau_m  = (const float*)d_in[3];
    const float* tau_g  = (const float*)d_in[4];
    const float* pre_c  = (const float*)d_in[5];
    const float* post_c = (const float*)d_in[6];
    const float* v0     = (const float*)d_in[7];
    const float* g0     = (const float*)d_in[8];
    float* out = (float*)d_out;

    lif_init_kernel<<<(NN + 255) / 256, 256>>>(g0);
    lif_persistent_kernel<<<NCTA, NTHR>>>(x_in, w, v_rest, tau_m, tau_g,
                                          pre_c, post_c, v0, g0, out);
}

// round 11
// speedup vs baseline: 1.2697x; 1.2697x over previous
#include <cuda_runtime.h>

#define T_STEPS 8192
#define NN      2048
#define NCTA    128
#define ROWS    16      // neurons (w rows) per CTA
#define NTHR    256     // threads per CTA (8 warps)
#define CPT     8       // columns per thread (2048 / 256)

// Parity double-buffered conductance + one monotonic arrival counter.
__device__ float g_buf[2][NN];
__device__ unsigned int bar_ctr;   // total arrivals = NCTA * (steps completed)

// Reset state so every graph replay is identical.
__global__ void lif_init_kernel(const float* __restrict__ g0) {
    int i = blockIdx.x * blockDim.x + threadIdx.x;
    if (i < NN) g_buf[0][i] = g0[i];
    if (i == 0) bar_ctr = 0;
}

__global__ void __launch_bounds__(NTHR, 1) lif_persistent_kernel(
    const float* __restrict__ x_in,    // [T, N]
    const float* __restrict__ w,       // [N, N] row-major
    const float* __restrict__ v_rest,  // [N]
    const float* __restrict__ tau_m,   // [N]
    const float* __restrict__ tau_g,   // [N]
    const float* __restrict__ pre_c_p, // [1]
    const float* __restrict__ post_c_p,// [1]
    const float* __restrict__ v0,      // [N]
    const float* __restrict__ g0,      // [N]
    float* __restrict__ out)           // [2, T, N]
{
    const int tid  = threadIdx.x;
    const int cta  = blockIdx.x;
    const int lane = tid & 31;
    const int warp = tid >> 5;
    const int row0 = cta * ROWS;
    const int col0 = tid * CPT;

    // Parity double-buffered per-warp row partials.
    __shared__ float sh_part[2][8][ROWS];

    // ---- one-time: this CTA's 16 w rows live in REGISTERS (128 KB/SM) ----
    float wreg[ROWS][CPT];
    #pragma unroll
    for (int r = 0; r < ROWS; r++) {
        const float4* wp = reinterpret_cast<const float4*>(
            w + (size_t)(row0 + r) * NN + col0);
        float4 a = wp[0], b = wp[1];
        wreg[r][0] = a.x; wreg[r][1] = a.y; wreg[r][2] = a.z; wreg[r][3] = a.w;
        wreg[r][4] = b.x; wreg[r][5] = b.y; wreg[r][6] = b.z; wreg[r][7] = b.w;
    }

    // ---- per-neuron state; ONLY change vs R5: divisions hoisted ----
    // tau_m = 4.0, tau_g = 2.0 (powers of two) -> reciprocal forms bit-exact.
    const float pre_c  = pre_c_p[0];
    const float post_c = post_c_p[0];
    float my_v = 0.f, my_g = 0.f, my_vrest = 0.f, inv_taum = 0.f, decay_g = 0.f;
    float x_next = 0.f;
    if (tid < ROWS) {
        int i = row0 + tid;
        my_v     = v0[i];
        my_g     = g0[i];
        my_vrest = v_rest[i];
        inv_taum = 1.0f / tau_m[i];
        decay_g  = 1.0f - 1.0f / tau_g[i];
        x_next   = __ldcs(&x_in[i]);   // prefetch x for t=0
    }
    __syncthreads();

    for (int t = 0; t < T_STEPS; t++) {
        const int par = t & 1;

        // ---- wait until all CTAs finished step t-1 (counter = NCTA*t) ----
        // R5-proven: ONE poller per CTA, plain .cg spin, nothing queued ahead.
        if (t > 0) {
            if (tid == 0) {
                const unsigned target = (unsigned)(NCTA * t);
                unsigned c;
                do {
                    asm volatile("ld.global.cg.u32 %0, [%1];"
                                 : "=r"(c) : "l"(&bar_ctr));
                } while (c < target);
            }
            __syncthreads();
        }

        // ---- load g for this step (L1-bypass; written by other SMs) ----
        float gv[CPT];
        {
            const float4 ga = __ldcg(reinterpret_cast<const float4*>(g_buf[par] + col0));
            const float4 gb = __ldcg(reinterpret_cast<const float4*>(g_buf[par] + col0 + 4));
            gv[0]=ga.x; gv[1]=ga.y; gv[2]=ga.z; gv[3]=ga.w;
            gv[4]=gb.x; gv[5]=gb.y; gv[6]=gb.z; gv[7]=gb.w;
        }

        // ---- prefetch next step's x AFTER the g load (R5 position: the DRAM
        // load hides under the matvec and never sits ahead of poll loads in
        // the L1tex completion FIFO) ----
        float x_cur = x_next;
        if (tid < ROWS && t + 1 < T_STEPS) {
            x_next = __ldcs(&x_in[(size_t)(t + 1) * NN + row0 + tid]);
        }

        // ---- matvec partials: 16 rows x 8 cols of register-resident w ----
        float acc[ROWS];
        #pragma unroll
        for (int r = 0; r < ROWS; r++) {
            float s = 0.f;
            #pragma unroll
            for (int k = 0; k < CPT; k++) s = fmaf(wreg[r][k], gv[k], s);
            acc[r] = s;
        }

        // ---- intra-warp folding reduction: 16 rows over 32 lanes, 16 SHFLs ----
        #pragma unroll
        for (int r = 0; r < 8; r++) {
            bool hi = (lane & 16) != 0;
            float send = hi ? acc[r] : acc[r + 8];
            float keep = hi ? acc[r + 8] : acc[r];
            acc[r] = keep + __shfl_xor_sync(0xffffffffu, send, 16);
        }
        #pragma unroll
        for (int r = 0; r < 4; r++) {
            bool hi = (lane & 8) != 0;
            float send = hi ? acc[r] : acc[r + 4];
            float keep = hi ? acc[r + 4] : acc[r];
            acc[r] = keep + __shfl_xor_sync(0xffffffffu, send, 8);
        }
        #pragma unroll
        for (int r = 0; r < 2; r++) {
            bool hi = (lane & 4) != 0;
            float send = hi ? acc[r] : acc[r + 2];
            float keep = hi ? acc[r + 2] : acc[r];
            acc[r] = keep + __shfl_xor_sync(0xffffffffu, send, 4);
        }
        {
            bool hi = (lane & 2) != 0;
            float send = hi ? acc[0] : acc[1];
            float keep = hi ? acc[1] : acc[0];
            acc[0] = keep + __shfl_xor_sync(0xffffffffu, send, 2);
        }
        acc[0] += __shfl_xor_sync(0xffffffffu, acc[0], 1);

        if ((lane & 1) == 0) sh_part[par][warp][lane >> 1] = acc[0];
        __syncthreads();

        // ---- LIF update (R5 ordering, division-free) + publish ----
        float v_new = 0.f, soft = 0.f;
        if (tid < ROWS) {
            float y = 0.f;
            #pragma unroll
            for (int wq = 0; wq < 8; wq++) y += sh_part[par][wq][tid];
            y += x_cur;

            float I = post_c / (1.f + expf(-pre_c * y));
            float gd = my_g * decay_g;                            // == g - g/tau_g (exact)
            float v  = my_v + ((my_vrest - my_v) + I) * inv_taum; // /4 == *0.25 (exact)
            soft = 1.f / (1.f + expf(-(v - 30.f)));
            bool spk = (v >= 30.f);
            v_new = spk ? my_vrest : v;
            float g_new = spk ? 1.f : gd;
            my_v = v_new;
            my_g = g_new;

            __stcg(&g_buf[(t + 1) & 1][row0 + tid], g_new);   // publish g
        }

        // Release (R5-proven): warp 0 fence covers the 16 g stores, tid0 arrives.
        if (warp == 0) __threadfence();
        if (tid == 0) atomicAdd(&bar_ctr, 1u);

        // Output traces AFTER the arrive — DRAM stores off the critical path.
        if (tid < ROWS) {
            int i = row0 + tid;
            __stcs(&out[(size_t)t * NN + i], v_new);
            __stcs(&out[(size_t)T_STEPS * NN + (size_t)t * NN + i], soft);
        }
        // No trailing CTA barrier: next iteration's poll + __syncthreads gates
        // every warp; g and sh_part are parity double-buffered.
    }
}

extern "C" void kernel_launch(void* const* d_in, const int* in_sizes, int n_in,
                              void* d_out, int out_size) {
    (void)in_sizes; (void)n_in; (void)out_size;
    const float* x_in   = (const float*)d_in[0];
    const float* w      = (const float*)d_in[1];
    const float* v_rest = (const float*)d_in[2];
    const float* tau_m  = (const float*)d_in[3];
    const float* tau_g  = (const float*)d_in[4];
    const float* pre_c  = (const float*)d_in[5];
    const float* post_c = (const float*)d_in[6];
    const float* v0     = (const float*)d_in[7];
    const float* g0     = (const float*)d_in[8];
    float* out = (float*)d_out;

    lif_init_kernel<<<(NN + 255) / 256, 256>>>(g0);
    lif_persistent_kernel<<<NCTA, NTHR>>>(x_in, w, v_rest, tau_m, tau_g,
                                          pre_c, post_c, v0, g0, out);
}